// round 5
// baseline (speedup 1.0000x reference)
#include <cuda_runtime.h>
#include <math.h>

// ----------------------------------------------------------------------------
// Fully fused: margin ranking loss (all i<j pairs) + weighted BCE, B=8192.
// labels in {0,1}:
//   equal-label pairs: contribute relu(m) each -> closed form from n1
//   mixed pairs:       relu(m - p_pos + p_neg)
// Decomposition: block b owns RAW indices [b*islice, ...) as the "pos" side
// (non-positives poisoned +1e30 -> fmax kills them); negs compacted into smem
// per block (deterministic, no atomics), tail poisoned -1e30.
// ----------------------------------------------------------------------------

#define G     128
#define T     512           // 16 warps
#define MAXB  8192
#define SLOTS (MAXB + 64)

__device__ double   g_mix[G];
__device__ double   g_bce[G];
__device__ unsigned g_done = 0;

__device__ __forceinline__ float read_margin(const void* p) {
    if (p == nullptr) return 1.0f;
    int v = *(const int*)p;
    if (v >= -1000000 && v <= 1000000) return (float)v;   // int scalar
    return __int_as_float(v);                             // float bits
}

__global__ void __launch_bounds__(T)
fused(const float* __restrict__ preds,
      const float* __restrict__ labels,
      const float* __restrict__ logits,
      const float* __restrict__ targets,
      const float* __restrict__ pw_,
      int n, const void* __restrict__ marginp,
      float* __restrict__ out)
{
    __shared__ __align__(16) float sneg[SLOTS];
    __shared__ int    wcnt[16], wbase[17];
    __shared__ double wm[16], wb[16];
    __shared__ int    isLast;

    const int tid  = threadIdx.x;
    const int lane = tid & 31;
    const int w    = tid >> 5;            // warp 0..15
    const float m  = read_margin(marginp);

    // ---- pass 1: warp w counts negs in its region [w*512, w*512+512) ------
    float    pr[16];
    unsigned savedBm = 0;                  // lane k keeps ballot of chunk k
    int      cnt = 0;
    const int rbase = w * 512;
    #pragma unroll
    for (int k = 0; k < 16; k++) {
        const int  c  = rbase + k * 32 + lane;
        const bool in = (c < n);
        float p = 0.f; bool neg = false;
        if (in) { p = preds[c]; neg = (labels[c] <= 0.5f); }
        pr[k] = p;
        const unsigned bm = __ballot_sync(0xffffffffu, in && neg);
        if (lane == k) savedBm = bm;
        cnt += __popc(bm);
    }
    if (lane == 0) wcnt[w] = cnt;
    __syncthreads();

    // ---- warp 0: exclusive scan of the 16 warp counts ----------------------
    if (w == 0 && lane < 16) {
        const int v = wcnt[lane];
        int x = v;
        #pragma unroll
        for (int off = 1; off < 16; off <<= 1) {
            const int y = __shfl_up_sync(0x0000ffffu, x, off);
            if (lane >= off) x += y;
        }
        wbase[lane] = x - v;
        if (lane == 15) wbase[16] = x;     // total n0
    }
    __syncthreads();
    const int n0 = wbase[16];
    const int n1 = n - n0;

    // ---- pass 2: deterministic scatter of negs (pre-add margin) -----------
    {
        int basep = wbase[w];
        #pragma unroll
        for (int k = 0; k < 16; k++) {
            const unsigned bm = __shfl_sync(0xffffffffu, savedBm, k);
            if ((bm >> lane) & 1u)
                sneg[basep + __popc(bm & ((1u << lane) - 1u))] = m + pr[k];
            basep += __popc(bm);
        }
    }
    // poison pad (covers up to 8*jchunk <= n0+63)
    for (int i = n0 + tid; i < n0 + 64 && i < SLOTS; i += T)
        sneg[i] = -1e30f;

    // ---- BCE over this block's raw slice ----------------------------------
    const int islice = (n + G - 1) / G;     // 64 for B=8192
    const int ibase  = blockIdx.x * islice;
    float bce = 0.f;
    for (int ii = tid; ii < islice; ii += T) {
        const int i = ibase + ii;
        if (i < n) {
            const float x  = logits[i];
            const float t  = targets[i];
            const float pw = pw_[0];
            const float mv = fmaxf(-x, 0.0f);
            const float sp = __logf(__expf(-mv) + __expf(-x - mv)) + mv;
            bce += (1.0f - t) * x + (1.0f + (pw - 1.0f) * t) * sp;
        }
    }
    __syncthreads();                        // sneg + pad ready

    // ---- pair phase: a = this thread's raw-slice element (poison +1e30) ---
    const int r      = tid >> 6;                       // j-range 0..7
    const int jchunk = (((n0 + 7) >> 3) + 7) & ~7;     // multiple of 8
    const int js     = r * jchunk;

    float s0 = 0.f, s1 = 0.f;
    for (int ia = (tid & 63); ia < islice; ia += 64) {
        const int aidx = ibase + ia;
        float a = 1e30f;
        if (aidx < n && labels[aidx] > 0.5f) a = preds[aidx];
        for (int jj = js; jj < js + jchunk; jj += 8) {
            const float4 t0 = *(const float4*)&sneg[jj];
            const float4 t1 = *(const float4*)&sneg[jj + 4];
            s0 += (fmaxf(t0.x - a, 0.f) + fmaxf(t0.y - a, 0.f))
                + (fmaxf(t0.z - a, 0.f) + fmaxf(t0.w - a, 0.f));
            s1 += (fmaxf(t1.x - a, 0.f) + fmaxf(t1.y - a, 0.f))
                + (fmaxf(t1.z - a, 0.f) + fmaxf(t1.w - a, 0.f));
        }
    }

    // ---- block reduce (mix + bce), publish partials -----------------------
    double dmix = (double)(s0 + s1);
    double dbce = (double)bce;
    #pragma unroll
    for (int off = 16; off; off >>= 1) {
        dmix += __shfl_down_sync(0xffffffffu, dmix, off);
        dbce += __shfl_down_sync(0xffffffffu, dbce, off);
    }
    if (lane == 0) { wm[w] = dmix; wb[w] = dbce; }
    __syncthreads();
    if (w == 0) {
        double vm = (lane < 16) ? wm[lane] : 0.0;
        double vb = (lane < 16) ? wb[lane] : 0.0;
        #pragma unroll
        for (int off = 8; off; off >>= 1) {
            vm += __shfl_down_sync(0xffffffffu, vm, off);
            vb += __shfl_down_sync(0xffffffffu, vb, off);
        }
        if (lane == 0) {
            g_mix[blockIdx.x] = vm;
            g_bce[blockIdx.x] = vb;
            __threadfence();
            isLast = (atomicAdd(&g_done, 1u) == (unsigned)G - 1u) ? 1 : 0;
        }
    }
    __syncthreads();

    // ---- last block: final reduce + outputs + reset -----------------------
    if (isLast) {
        double fm = 0.0, fb = 0.0;
        for (int i = tid; i < G; i += T) {
            fm += __ldcg(&g_mix[i]);
            fb += __ldcg(&g_bce[i]);
        }
        #pragma unroll
        for (int off = 16; off; off >>= 1) {
            fm += __shfl_down_sync(0xffffffffu, fm, off);
            fb += __shfl_down_sync(0xffffffffu, fb, off);
        }
        if (lane == 0) { wm[w] = fm; wb[w] = fb; }
        __syncthreads();
        if (tid == 0) {
            double sm = 0.0, sb = 0.0;
            #pragma unroll
            for (int k = 0; k < 16; k++) { sm += wm[k]; sb += wb[k]; }
            const double dn1 = (double)n1, dn0 = (double)n0;
            const double eqPairs = 0.5 * (dn1 * (dn1 - 1.0) + dn0 * (dn0 - 1.0));
            const double mm = (m > 0.0f) ? (double)m : 0.0;
            out[0] = (float)((mm * eqPairs + sm) / (double)n);
            out[1] = (float)(sb / (double)n);
            g_done = 0u;                    // only persistent state to reset
        }
    }
}

// ---------------------------------------------------------------------------
extern "C" void kernel_launch(void* const* d_in, const int* in_sizes, int n_in,
                              void* d_out, int out_size)
{
    const float* preds   = (const float*)d_in[0];
    const float* labels  = (const float*)d_in[1];
    const float* logits  = (const float*)d_in[2];
    const float* targets = (const float*)d_in[3];
    const float* pw      = (const float*)d_in[4];
    const void*  marginp = (n_in >= 6) ? d_in[5] : nullptr;
    const int n = in_sizes[0];
    float* out = (float*)d_out;

    fused<<<G, T>>>(preds, labels, logits, targets, pw, n, marginp, out);
}

// round 7
// speedup vs baseline: 1.2124x; 1.2124x over previous
#include <cuda_runtime.h>
#include <math.h>

// ----------------------------------------------------------------------------
// Fully fused, zero-redundancy: margin ranking loss (all i<j) + weighted BCE.
// labels in {0,1}:
//   equal-label pairs: contribute relu(m) each -> closed form from n1
//   mixed pairs:       relu((m + p_neg) - p_pos)
// 2-D tiling by RAW index: block (x,y) = (pos from x-slice) x (neg from y-slice).
// Per-block warp-aggregated smem-atomic compaction (order-free; sums commute).
// ----------------------------------------------------------------------------

#define GXX 16
#define GYY 37
#define G   (GXX * GYY)        // 592 blocks = 4 per SM on 148 SMs
#define T   256                // 8 warps
#define SXMAX 512              // ceil(8192/16)
#define SYPAD 232              // ceil(8192/37)=222 -> +8-pad, mult of 8

__device__ double   g_mix[G];
__device__ double   g_bce[G];
__device__ int      g_n1   = 0;
__device__ unsigned g_done = 0;

__device__ __forceinline__ float read_margin(const void* p) {
    if (p == nullptr) return 1.0f;
    int v = *(const int*)p;
    if (v >= -1000000 && v <= 1000000) return (float)v;   // int scalar
    return __int_as_float(v);                             // float bits
}

__global__ void __launch_bounds__(T)
fused(const float* __restrict__ preds,
      const float* __restrict__ labels,
      const float* __restrict__ logits,
      const float* __restrict__ targets,
      const float* __restrict__ pw_,
      int n, const void* __restrict__ marginp,
      float* __restrict__ out)
{
    __shared__ __align__(16) float sneg[SYPAD];
    __shared__ float  spos[SXMAX];
    __shared__ int    cntNeg, cntPos;
    __shared__ double wm[8], wb[8];
    __shared__ int    isLast;

    const int tid  = threadIdx.x;
    const int lane = tid & 31;
    const int w    = tid >> 5;
    const int bx   = blockIdx.x, by = blockIdx.y;
    const int bid  = by * GXX + bx;
    const float m  = read_margin(marginp);
    const float pw = pw_[0];

    // ---- init: counters + pre-poison neg tile -----------------------------
    if (tid == 0) { cntNeg = 0; cntPos = 0; }
    for (int i = tid; i < SYPAD; i += T) sneg[i] = -1e30f;
    __syncthreads();

    // ---- compact negs of raw y-slice into sneg (store m + p) --------------
    const int sy = (n + GYY - 1) / GYY;
    const int ys = by * sy;
    const int ylen = max(min(sy, n - ys), 0);
    for (int i0 = 0; i0 < ylen; i0 += T) {
        const int  i  = i0 + tid;
        const bool in = (i < ylen);
        float p = 0.f; bool neg = false;
        if (in) { p = preds[ys + i]; neg = (labels[ys + i] <= 0.5f); }
        const unsigned bm   = __ballot_sync(0xffffffffu, neg);
        const int      rank = __popc(bm & ((1u << lane) - 1u));
        int base = 0;
        if (lane == 0) base = atomicAdd(&cntNeg, __popc(bm));
        base = __shfl_sync(0xffffffffu, base, 0);
        if (neg) sneg[base + rank] = m + p;
    }

    // ---- compact pos of raw x-slice into spos -----------------------------
    const int sx = (n + GXX - 1) / GXX;
    const int xs = bx * sx;
    const int xlen = max(min(sx, n - xs), 0);
    for (int i0 = 0; i0 < xlen; i0 += T) {
        const int  i  = i0 + tid;
        const bool in = (i < xlen);
        float p = 0.f; bool pos = false;
        if (in) { p = preds[xs + i]; pos = (labels[xs + i] > 0.5f); }
        const unsigned bm   = __ballot_sync(0xffffffffu, pos);
        const int      rank = __popc(bm & ((1u << lane) - 1u));
        int base = 0;
        if (lane == 0) base = atomicAdd(&cntPos, __popc(bm));
        base = __shfl_sync(0xffffffffu, base, 0);
        if (pos) spos[base + rank] = p;
    }

    // ---- BCE over this block's private 1/G slice --------------------------
    const int islice = (n + G - 1) / G;          // 14 for B=8192
    const int ib = bid * islice;
    float bce = 0.f;
    for (int ii = tid; ii < islice; ii += T) {
        const int i = ib + ii;
        if (i < n) {
            const float x  = logits[i];
            const float t  = targets[i];
            const float mv = fmaxf(-x, 0.0f);
            const float sp = __logf(__expf(-mv) + __expf(-x - mv)) + mv;
            bce += (1.0f - t) * x + (1.0f + (pw - 1.0f) * t) * sp;
        }
    }
    __syncthreads();

    const int cp  = cntPos;
    const int cn  = cntNeg;
    const int cn8 = (cn + 7) & ~7;               // tail poisoned (-1e30 -> 0)

    // ---- pair phase: thread sa -> one pos; stream negs from smem ----------
    float s0 = 0.f, s1 = 0.f;
    for (int sa = tid; sa < cp; sa += T) {
        const float a = spos[sa];
        for (int j = 0; j < cn8; j += 8) {
            const float4 t0 = *(const float4*)&sneg[j];
            const float4 t1 = *(const float4*)&sneg[j + 4];
            s0 += (fmaxf(t0.x - a, 0.f) + fmaxf(t0.y - a, 0.f))
                + (fmaxf(t0.z - a, 0.f) + fmaxf(t0.w - a, 0.f));
            s1 += (fmaxf(t1.x - a, 0.f) + fmaxf(t1.y - a, 0.f))
                + (fmaxf(t1.z - a, 0.f) + fmaxf(t1.w - a, 0.f));
        }
    }

    // ---- block reduce + publish -------------------------------------------
    double dmix = (double)(s0 + s1);
    double dbce = (double)bce;
    #pragma unroll
    for (int off = 16; off; off >>= 1) {
        dmix += __shfl_down_sync(0xffffffffu, dmix, off);
        dbce += __shfl_down_sync(0xffffffffu, dbce, off);
    }
    if (lane == 0) { wm[w] = dmix; wb[w] = dbce; }
    __syncthreads();
    if (w == 0) {
        double vm = (lane < 8) ? wm[lane] : 0.0;
        double vb = (lane < 8) ? wb[lane] : 0.0;
        #pragma unroll
        for (int off = 4; off; off >>= 1) {
            vm += __shfl_down_sync(0xffffffffu, vm, off);
            vb += __shfl_down_sync(0xffffffffu, vb, off);
        }
        if (lane == 0) {
            g_mix[bid] = vm;
            g_bce[bid] = vb;
            if (by == 0) atomicAdd(&g_n1, cp);   // n1 counted once per x-slice
            __threadfence();
            isLast = (atomicAdd(&g_done, 1u) == (unsigned)G - 1u) ? 1 : 0;
        }
    }
    __syncthreads();

    // ---- last block: final reduce + outputs + reset -----------------------
    if (isLast) {
        double fm = 0.0, fb = 0.0;
        for (int i = tid; i < G; i += T) {
            fm += __ldcg(&g_mix[i]);
            fb += __ldcg(&g_bce[i]);
        }
        #pragma unroll
        for (int off = 16; off; off >>= 1) {
            fm += __shfl_down_sync(0xffffffffu, fm, off);
            fb += __shfl_down_sync(0xffffffffu, fb, off);
        }
        if (lane == 0) { wm[w] = fm; wb[w] = fb; }
        __syncthreads();
        if (tid == 0) {
            double sm = 0.0, sb = 0.0;
            #pragma unroll
            for (int k = 0; k < 8; k++) { sm += wm[k]; sb += wb[k]; }
            const int    n1  = g_n1;
            const double dn1 = (double)n1, dn0 = (double)(n - n1);
            const double eqPairs = 0.5 * (dn1 * (dn1 - 1.0) + dn0 * (dn0 - 1.0));
            const double mm = (m > 0.0f) ? (double)m : 0.0;
            out[0] = (float)((mm * eqPairs + sm) / (double)n);
            out[1] = (float)(sb / (double)n);
            g_n1   = 0;                          // reset for next replay
            g_done = 0u;
        }
    }
}

// ---------------------------------------------------------------------------
extern "C" void kernel_launch(void* const* d_in, const int* in_sizes, int n_in,
                              void* d_out, int out_size)
{
    const float* preds   = (const float*)d_in[0];
    const float* labels  = (const float*)d_in[1];
    const float* logits  = (const float*)d_in[2];
    const float* targets = (const float*)d_in[3];
    const float* pw      = (const float*)d_in[4];
    const void*  marginp = (n_in >= 6) ? d_in[5] : nullptr;
    const int n = in_sizes[0];
    float* out = (float*)d_out;

    fused<<<dim3(GXX, GYY), T>>>(preds, labels, logits, targets, pw, n,
                                 marginp, out);
}